// round 6
// baseline (speedup 1.0000x reference)
#include <cuda_runtime.h>

// ---------------- problem constants ----------------
#define B_    2
#define C_    64
#define H_    512
#define W_    512
#define T_    16
#define K_    1024          // tiles per sample
#define KMAX_ 256
#define HID_  128
#define HW_   (H_*W_)       // 262144
#define CHW_  (C_*HW_)      // 16777216

// output layout (flatten-concat of the tuple, all f32)
#define HEAVY_OFF  0
#define DET_OFF    33554432
#define ALPHA_OFF  67108864
#define P_OFF      67633152
#define G_OFF      67635200
#define COST_OFF   67637248
#define BL_OFF     67637249

__device__ int   g_sel[B_*K_];
__device__ float g_W1T[HID_*C_];   // [d][c]

typedef unsigned long long u64;

// ---------------- packed f32x2 helpers ----------------
__device__ __forceinline__ u64 pack2(float lo, float hi) {
    u64 r; asm("mov.b64 %0, {%1, %2};" : "=l"(r) : "f"(lo), "f"(hi)); return r;
}
__device__ __forceinline__ void unpack2(u64 v, float& lo, float& hi) {
    asm("mov.b64 {%0, %1}, %2;" : "=f"(lo), "=f"(hi) : "l"(v));
}
__device__ __forceinline__ u64 ffma2(u64 a, u64 b, u64 c) {
    u64 d; asm("fma.rn.f32x2 %0, %1, %2, %3;" : "=l"(d) : "l"(a), "l"(b), "l"(c));
    return d;
}
__device__ __forceinline__ u64 add2(u64 a, u64 b) {
    u64 d; asm("add.rn.f32x2 %0, %1, %2;" : "=l"(d) : "l"(a), "l"(b));
    return d;
}
__device__ __forceinline__ float hsum2(u64 v) {
    float lo, hi; unpack2(v, lo, hi); return lo + hi;
}

// ---------------- math helpers ----------------
__device__ __forceinline__ float fast_sigmoid(float v) {
    return __fdividef(1.f, 1.f + __expf(-v));
}
__device__ __forceinline__ float gelu_tanh(float v) {
    float z  = 0.7978845608028654f * fmaf(0.044715f * v, v * v, v);
    float th; asm("tanh.approx.f32 %0, %1;" : "=f"(th) : "f"(z));
    return 0.5f * v * (1.f + th);
}

// ---------------- prep kernel: select (blk 0-31) + gate (32) + W1T (33) ----
__global__ void __launch_bounds__(256)
prep_kernel(const float* __restrict__ u, const float* __restrict__ W1,
            float* __restrict__ out) {
    __shared__ float sh[64*129];
    int blk = blockIdx.x;
    int t   = threadIdx.x;

    if (blk < 32) {
        float* us = sh;
        int b   = blk >> 4;
        int seg = blk & 15;
        for (int i = t; i < K_; i += 256) us[i] = u[b*K_ + i];
        __syncthreads();
        int e   = seg*64 + (t >> 2);
        int sub = t & 3;
        float ue = us[e];
        int cnt = 0;
        if (ue >= 0.f) {
            int j0 = sub * 256;
            #pragma unroll 4
            for (int j = j0; j < j0 + 256; ++j) {
                float uj = us[j];
                if (uj >= 0.f && (uj > ue || (uj == ue && j < e))) cnt++;
            }
        }
        cnt += __shfl_xor_sync(0xFFFFFFFFu, cnt, 1);
        cnt += __shfl_xor_sync(0xFFFFFFFFu, cnt, 2);
        if (sub == 0) g_sel[b*K_ + e] = (ue >= 0.f && cnt < KMAX_) ? 1 : 0;
    } else if (blk == 32) {
        float partial = 0.f;
        #pragma unroll
        for (int e = t; e < B_*K_; e += 256) {
            float uv = u[e];
            float p  = fast_sigmoid(uv);
            float hard = (uv >= 0.f) ? 1.f : 0.f;
            float gate = (hard + p) - p;
            out[P_OFF + e] = p;
            out[G_OFF + e] = gate;
            partial += fmaf(p, 0.9f, 0.1f);
        }
        #pragma unroll
        for (int s = 16; s > 0; s >>= 1)
            partial += __shfl_xor_sync(0xFFFFFFFFu, partial, s);
        if ((t & 31) == 0) sh[t >> 5] = partial;
        __syncthreads();
        if (t == 0) {
            float cost = 0.f;
            #pragma unroll
            for (int w = 0; w < 8; ++w) cost += sh[w];
            out[COST_OFF] = cost;
            float bl = cost - 1024.f;
            out[BL_OFF] = bl > 0.f ? bl : 0.f;
        }
    } else {
        for (int i = t; i < C_*HID_; i += 256) {
            int c = i >> 7, d = i & 127;
            sh[c*129 + d] = W1[i];
        }
        __syncthreads();
        for (int i = t; i < C_*HID_; i += 256) {
            int d = i >> 6, c = i & 63;
            g_W1T[i] = sh[c*129 + d];
        }
    }
}

// ---------------- main kernel ----------------
// grid = 2*B*K blocks (half-tile each), 256 threads, 2 blocks/SM.
// Heavy: lane quartet per pixel pair. lane = (q<<3)|p : quarter q owns
// channels [16q,16q+16), p indexes 8 pixel-pairs per warp. Thread handles
// pixels pxa = half*64 + w*8 + p and pxb = pxa+128. GEMM1 dots joined by
// shfl_xor(8) + shfl_xor(16) butterfly. Weight rows stored as 4 chunks of
// 16 floats at 20-float stride (16B aligned, conflict-free across quarters).
#define ROWP   80                  // padded row stride (floats)
#define CHK    20                  // per-quarter chunk stride
#define SM_W1  0                   // 128*80
#define SM_W2  10240               // 128*80
#define SM_B1  20480               // 128
#define SM_B2  20608               // 80
#define SM_WA  20688               // 80
#define SM_BA  20768
#define SMEM_FLOATS 20772
#define SMEM_BYTES (SMEM_FLOATS*4)

__global__ void __launch_bounds__(256, 2)
main_kernel(const float* __restrict__ x,
            const float* __restrict__ W2g, const float* __restrict__ b1,
            const float* __restrict__ b2, const float* __restrict__ Wa,
            const float* __restrict__ ba,
            float* __restrict__ out) {
    extern __shared__ float sm[];
    int blk  = blockIdx.x;
    int tile = blk >> 1;
    int half = blk & 1;
    int b    = tile >> 10;
    int k    = tile & (K_-1);
    int gh   = k >> 5, gw = k & 31;
    int t    = threadIdx.x;

    int tile_base = b*CHW_ + (gh*T_)*W_ + gw*T_;
    float* heavy = out + HEAVY_OFF;
    float* det   = out + DET_OFF;
    float* alp   = out + ALPHA_OFF;

    if (!g_sel[tile]) {
        // ---- cheap path: 128 px (rows [half*8, half*8+8)) ----
        int rbase = half*8;
        #pragma unroll 8
        for (int i = t; i < 2048; i += 256) {
            int c = i >> 5; int l = i & 31;
            int off = tile_base + c*HW_ + (rbase + (l >> 2))*W_ + (l & 3)*4;
            float4 v = *(const float4*)(x + off);
            *(float4*)(heavy + off) = v;
            *(float4*)(det   + off) = make_float4(0.f,0.f,0.f,0.f);
        }
        if (t < 32) {
            int aoff = b*HW_ + (gh*T_ + rbase + (t >> 2))*W_ + gw*T_ + (t & 3)*4;
            *(float4*)(alp + aoff) = make_float4(0.f,0.f,0.f,0.f);
        }
        return;
    }

    // ---- stage weights: 4 chunks of 16 floats per row, stride 20 ----
    for (int i = t; i < HID_*C_; i += 256) {
        int d = i >> 6, c = i & 63;
        int dst = d*ROWP + (c >> 4)*CHK + (c & 15);
        sm[SM_W1 + dst] = g_W1T[i];
        sm[SM_W2 + dst] = W2g[i];
    }
    if (t < HID_) sm[SM_B1 + t] = b1[t];
    if (t < C_) {
        int dst = (t >> 4)*CHK + (t & 15);
        sm[SM_B2 + dst] = b2[t];
        sm[SM_WA + dst] = Wa[t];
    }
    if (t == 0) sm[SM_BA] = ba[0];
    __syncthreads();

    int lane = t & 31;
    int q    = lane >> 3;                 // channel quarter 0..3
    int p    = lane & 7;                  // pixel-pair slot in warp
    int w    = t >> 5;
    int pxa  = half*64 + w*8 + p;         // 0..127 ; pxb = pxa+128
    int ra   = pxa >> 4, cpos = pxa & 15;
    int pbaseA = tile_base + ra*W_ + cpos;
    int pbaseB = pbaseA + 8*W_;
    int cbase  = q*16;
    int woff   = q*CHK;

    // x for both pixels, this thread's 16 channels, packed into 8 f32x2
    u64 xa2[8], xb2[8];
    #pragma unroll
    for (int j = 0; j < 8; ++j) {
        int o = (cbase + 2*j)*HW_;
        xa2[j] = pack2(x[pbaseA + o], x[pbaseA + o + HW_]);
        xb2[j] = pack2(x[pbaseB + o], x[pbaseB + o + HW_]);
    }

    // alpha for both pixels (quarter-dot + butterfly)
    float alphaA, alphaB;
    {
        const ulonglong2* war = (const ulonglong2*)(sm + SM_WA + woff);
        ulonglong2 w0 = war[0], w1 = war[1], w2v = war[2], w3 = war[3];
        u64 a0=0, a1=0, c0=0, c1=0;
        a0 = ffma2(xa2[0], w0.x, a0); a1 = ffma2(xa2[1], w0.y, a1);
        a0 = ffma2(xa2[2], w1.x, a0); a1 = ffma2(xa2[3], w1.y, a1);
        a0 = ffma2(xa2[4], w2v.x, a0); a1 = ffma2(xa2[5], w2v.y, a1);
        a0 = ffma2(xa2[6], w3.x, a0); a1 = ffma2(xa2[7], w3.y, a1);
        c0 = ffma2(xb2[0], w0.x, c0); c1 = ffma2(xb2[1], w0.y, c1);
        c0 = ffma2(xb2[2], w1.x, c0); c1 = ffma2(xb2[3], w1.y, c1);
        c0 = ffma2(xb2[4], w2v.x, c0); c1 = ffma2(xb2[5], w2v.y, c1);
        c0 = ffma2(xb2[6], w3.x, c0); c1 = ffma2(xb2[7], w3.y, c1);
        float pa = hsum2(add2(a0, a1));
        float pb = hsum2(add2(c0, c1));
        pa += __shfl_xor_sync(0xFFFFFFFFu, pa, 8);
        pa += __shfl_xor_sync(0xFFFFFFFFu, pa, 16);
        pb += __shfl_xor_sync(0xFFFFFFFFu, pb, 8);
        pb += __shfl_xor_sync(0xFFFFFFFFu, pb, 16);
        alphaA = fast_sigmoid(pa + sm[SM_BA]);
        alphaB = fast_sigmoid(pb + sm[SM_BA]);
    }

    // accumulators: 16 out-channels per pixel
    u64 acca[8], accb[8];
    #pragma unroll
    for (int j = 0; j < 8; ++j) {
        u64 bb = pack2(sm[SM_B2 + woff + 2*j], sm[SM_B2 + woff + 2*j + 1]);
        acca[j] = bb; accb[j] = bb;
    }

    const float* smW1 = sm + SM_W1 + woff;
    const float* smW2 = sm + SM_W2 + woff;

    for (int d = 0; d < HID_; d += 2) {
        const ulonglong2* w1r0 = (const ulonglong2*)(smW1 + d*ROWP);
        const ulonglong2* w1r1 = (const ulonglong2*)(smW1 + d*ROWP + ROWP);
        ulonglong2 p0 = w1r0[0], p1 = w1r0[1], p2 = w1r0[2], p3 = w1r0[3];
        ulonglong2 q0 = w1r1[0], q1 = w1r1[1], q2 = w1r1[2], q3 = w1r1[3];
        // 4 quarter-dots: rows {d,d+1} x px {a,b}
        u64 da0=0,da1=0, db0=0,db1=0, ea0=0,ea1=0, eb0=0,eb1=0;
        da0=ffma2(xa2[0],p0.x,da0); da1=ffma2(xa2[1],p0.y,da1);
        da0=ffma2(xa2[2],p1.x,da0); da1=ffma2(xa2[3],p1.y,da1);
        da0=ffma2(xa2[4],p2.x,da0); da1=ffma2(xa2[5],p2.y,da1);
        da0=ffma2(xa2[6],p3.x,da0); da1=ffma2(xa2[7],p3.y,da1);
        db0=ffma2(xb2[0],p0.x,db0); db1=ffma2(xb2[1],p0.y,db1);
        db0=ffma2(xb2[2],p1.x,db0); db1=ffma2(xb2[3],p1.y,db1);
        db0=ffma2(xb2[4],p2.x,db0); db1=ffma2(xb2[5],p2.y,db1);
        db0=ffma2(xb2[6],p3.x,db0); db1=ffma2(xb2[7],p3.y,db1);
        ea0=ffma2(xa2[0],q0.x,ea0); ea1=ffma2(xa2[1],q0.y,ea1);
        ea0=ffma2(xa2[2],q1.x,ea0); ea1=ffma2(xa2[3],q1.y,ea1);
        ea0=ffma2(xa2[4],q2.x,ea0); ea1=ffma2(xa2[5],q2.y,ea1);
        ea0=ffma2(xa2[6],q3.x,ea0); ea1=ffma2(xa2[7],q3.y,ea1);
        eb0=ffma2(xb2[0],q0.x,eb0); eb1=ffma2(xb2[1],q0.y,eb1);
        eb0=ffma2(xb2[2],q1.x,eb0); eb1=ffma2(xb2[3],q1.y,eb1);
        eb0=ffma2(xb2[4],q2.x,eb0); eb1=ffma2(xb2[5],q2.y,eb1);
        eb0=ffma2(xb2[6],q3.x,eb0); eb1=ffma2(xb2[7],q3.y,eb1);
        float rA0 = hsum2(add2(da0, da1));
        float rB0 = hsum2(add2(db0, db1));
        float rA1 = hsum2(add2(ea0, ea1));
        float rB1 = hsum2(add2(eb0, eb1));
        rA0 += __shfl_xor_sync(0xFFFFFFFFu, rA0, 8);
        rA0 += __shfl_xor_sync(0xFFFFFFFFu, rA0, 16);
        rB0 += __shfl_xor_sync(0xFFFFFFFFu, rB0, 8);
        rB0 += __shfl_xor_sync(0xFFFFFFFFu, rB0, 16);
        rA1 += __shfl_xor_sync(0xFFFFFFFFu, rA1, 8);
        rA1 += __shfl_xor_sync(0xFFFFFFFFu, rA1, 16);
        rB1 += __shfl_xor_sync(0xFFFFFFFFu, rB1, 8);
        rB1 += __shfl_xor_sync(0xFFFFFFFFu, rB1, 16);
        float bi0 = sm[SM_B1 + d], bi1 = sm[SM_B1 + d + 1];
        float hA0 = gelu_tanh(rA0 + bi0);
        float hB0 = gelu_tanh(rB0 + bi0);
        float hA1 = gelu_tanh(rA1 + bi1);
        float hB1 = gelu_tanh(rB1 + bi1);
        u64 hA02 = pack2(hA0, hA0), hA12 = pack2(hA1, hA1);
        u64 hB02 = pack2(hB0, hB0), hB12 = pack2(hB1, hB1);
        const ulonglong2* w2r0 = (const ulonglong2*)(smW2 + d*ROWP);
        const ulonglong2* w2r1 = (const ulonglong2*)(smW2 + d*ROWP + ROWP);
        ulonglong2 r0 = w2r0[0], r1 = w2r0[1], r2 = w2r0[2], r3 = w2r0[3];
        ulonglong2 s0 = w2r1[0], s1 = w2r1[1], s2 = w2r1[2], s3 = w2r1[3];
        acca[0] = ffma2(hA02, r0.x, acca[0]); acca[1] = ffma2(hA02, r0.y, acca[1]);
        acca[2] = ffma2(hA02, r1.x, acca[2]); acca[3] = ffma2(hA02, r1.y, acca[3]);
        acca[4] = ffma2(hA02, r2.x, acca[4]); acca[5] = ffma2(hA02, r2.y, acca[5]);
        acca[6] = ffma2(hA02, r3.x, acca[6]); acca[7] = ffma2(hA02, r3.y, acca[7]);
        acca[0] = ffma2(hA12, s0.x, acca[0]); acca[1] = ffma2(hA12, s0.y, acca[1]);
        acca[2] = ffma2(hA12, s1.x, acca[2]); acca[3] = ffma2(hA12, s1.y, acca[3]);
        acca[4] = ffma2(hA12, s2.x, acca[4]); acca[5] = ffma2(hA12, s2.y, acca[5]);
        acca[6] = ffma2(hA12, s3.x, acca[6]); acca[7] = ffma2(hA12, s3.y, acca[7]);
        accb[0] = ffma2(hB02, r0.x, accb[0]); accb[1] = ffma2(hB02, r0.y, accb[1]);
        accb[2] = ffma2(hB02, r1.x, accb[2]); accb[3] = ffma2(hB02, r1.y, accb[3]);
        accb[4] = ffma2(hB02, r2.x, accb[4]); accb[5] = ffma2(hB02, r2.y, accb[5]);
        accb[6] = ffma2(hB02, r3.x, accb[6]); accb[7] = ffma2(hB02, r3.y, accb[7]);
        accb[0] = ffma2(hB12, s0.x, accb[0]); accb[1] = ffma2(hB12, s0.y, accb[1]);
        accb[2] = ffma2(hB12, s1.x, accb[2]); accb[3] = ffma2(hB12, s1.y, accb[3]);
        accb[4] = ffma2(hB12, s2.x, accb[4]); accb[5] = ffma2(hB12, s2.y, accb[5]);
        accb[6] = ffma2(hB12, s3.x, accb[6]); accb[7] = ffma2(hB12, s3.y, accb[7]);
    }

    if (q == 0) {
        int arow = b*HW_ + (gh*T_ + ra)*W_ + gw*T_ + cpos;
        alp[arow] = alphaA;
        alp[arow + 8*W_] = alphaB;
    }
    #pragma unroll
    for (int j = 0; j < 8; ++j) {
        int o = (cbase + 2*j)*HW_;
        float d0, d1, x0, x1;
        unpack2(acca[j], d0, d1);
        unpack2(xa2[j],  x0, x1);
        det[pbaseA + o]        = d0;
        det[pbaseA + o + HW_]  = d1;
        heavy[pbaseA + o]       = fmaf(alphaA, d0, x0);
        heavy[pbaseA + o + HW_] = fmaf(alphaA, d1, x1);
        unpack2(accb[j], d0, d1);
        unpack2(xb2[j],  x0, x1);
        det[pbaseB + o]        = d0;
        det[pbaseB + o + HW_]  = d1;
        heavy[pbaseB + o]       = fmaf(alphaB, d0, x0);
        heavy[pbaseB + o + HW_] = fmaf(alphaB, d1, x1);
    }
}

// ---------------- launcher ----------------
extern "C" void kernel_launch(void* const* d_in, const int* in_sizes, int n_in,
                              void* d_out, int out_size) {
    const float* x  = (const float*)d_in[0];
    const float* u  = (const float*)d_in[1];
    const float* W1 = (const float*)d_in[2];
    const float* b1 = (const float*)d_in[3];
    const float* W2 = (const float*)d_in[4];
    const float* b2 = (const float*)d_in[5];
    const float* Wa = (const float*)d_in[6];
    const float* ba = (const float*)d_in[7];
    float* out = (float*)d_out;

    cudaFuncSetAttribute(main_kernel,
                         cudaFuncAttributeMaxDynamicSharedMemorySize, SMEM_BYTES);

    prep_kernel<<<34, 256>>>(u, W1, out);
    main_kernel<<<2*B_*K_, 256, SMEM_BYTES>>>(x, W2, b1, b2, Wa, ba, out);
}

// round 7
// speedup vs baseline: 1.0051x; 1.0051x over previous
#include <cuda_runtime.h>

// ---------------- problem constants ----------------
#define B_    2
#define C_    64
#define H_    512
#define W_    512
#define T_    16
#define K_    1024          // tiles per sample
#define KMAX_ 256
#define HID_  128
#define HW_   (H_*W_)       // 262144
#define CHW_  (C_*HW_)      // 16777216

// output layout (flatten-concat of the tuple, all f32)
#define HEAVY_OFF  0
#define DET_OFF    33554432
#define ALPHA_OFF  67108864
#define P_OFF      67633152
#define G_OFF      67635200
#define COST_OFF   67637248
#define BL_OFF     67637249

__device__ int   g_sel[B_*K_];
__device__ float g_W1T[HID_*C_];   // [d][c]

typedef unsigned long long u64;

// ---------------- packed f32x2 helpers ----------------
__device__ __forceinline__ u64 pack2(float lo, float hi) {
    u64 r; asm("mov.b64 %0, {%1, %2};" : "=l"(r) : "f"(lo), "f"(hi)); return r;
}
__device__ __forceinline__ void unpack2(u64 v, float& lo, float& hi) {
    asm("mov.b64 {%0, %1}, %2;" : "=f"(lo), "=f"(hi) : "l"(v));
}
__device__ __forceinline__ u64 ffma2(u64 a, u64 b, u64 c) {
    u64 d; asm("fma.rn.f32x2 %0, %1, %2, %3;" : "=l"(d) : "l"(a), "l"(b), "l"(c));
    return d;
}
__device__ __forceinline__ u64 add2(u64 a, u64 b) {
    u64 d; asm("add.rn.f32x2 %0, %1, %2;" : "=l"(d) : "l"(a), "l"(b));
    return d;
}
__device__ __forceinline__ float hsum2(u64 v) {
    float lo, hi; unpack2(v, lo, hi); return lo + hi;
}

// ---------------- math helpers ----------------
__device__ __forceinline__ float fast_sigmoid(float v) {
    return __fdividef(1.f, 1.f + __expf(-v));
}
__device__ __forceinline__ float gelu_tanh(float v) {
    float z  = 0.7978845608028654f * fmaf(0.044715f * v, v * v, v);
    float th; asm("tanh.approx.f32 %0, %1;" : "=f"(th) : "f"(z));
    return 0.5f * v * (1.f + th);
}

// ---------------- prep kernel: select (blk 0-31) + gate (32) + W1T (33) ----
__global__ void __launch_bounds__(256)
prep_kernel(const float* __restrict__ u, const float* __restrict__ W1,
            float* __restrict__ out) {
    __shared__ float sh[64*129];
    int blk = blockIdx.x;
    int t   = threadIdx.x;

    if (blk < 32) {
        float* us = sh;
        int b   = blk >> 4;
        int seg = blk & 15;
        for (int i = t; i < K_; i += 256) us[i] = u[b*K_ + i];
        __syncthreads();
        int e   = seg*64 + (t >> 2);
        int sub = t & 3;
        float ue = us[e];
        int cnt = 0;
        if (ue >= 0.f) {
            int j0 = sub * 256;
            #pragma unroll 4
            for (int j = j0; j < j0 + 256; ++j) {
                float uj = us[j];
                if (uj >= 0.f && (uj > ue || (uj == ue && j < e))) cnt++;
            }
        }
        cnt += __shfl_xor_sync(0xFFFFFFFFu, cnt, 1);
        cnt += __shfl_xor_sync(0xFFFFFFFFu, cnt, 2);
        if (sub == 0) g_sel[b*K_ + e] = (ue >= 0.f && cnt < KMAX_) ? 1 : 0;
    } else if (blk == 32) {
        float partial = 0.f;
        #pragma unroll
        for (int e = t; e < B_*K_; e += 256) {
            float uv = u[e];
            float p  = fast_sigmoid(uv);
            float hard = (uv >= 0.f) ? 1.f : 0.f;
            float gate = (hard + p) - p;
            out[P_OFF + e] = p;
            out[G_OFF + e] = gate;
            partial += fmaf(p, 0.9f, 0.1f);
        }
        #pragma unroll
        for (int s = 16; s > 0; s >>= 1)
            partial += __shfl_xor_sync(0xFFFFFFFFu, partial, s);
        if ((t & 31) == 0) sh[t >> 5] = partial;
        __syncthreads();
        if (t == 0) {
            float cost = 0.f;
            #pragma unroll
            for (int w = 0; w < 8; ++w) cost += sh[w];
            out[COST_OFF] = cost;
            float bl = cost - 1024.f;
            out[BL_OFF] = bl > 0.f ? bl : 0.f;
        }
    } else {
        for (int i = t; i < C_*HID_; i += 256) {
            int c = i >> 7, d = i & 127;
            sh[c*129 + d] = W1[i];
        }
        __syncthreads();
        for (int i = t; i < C_*HID_; i += 256) {
            int d = i >> 6, c = i & 63;
            g_W1T[i] = sh[c*129 + d];
        }
    }
}

// ---------------- main kernel ----------------
// grid = 2*B*K blocks (half-tile each), 256 threads, 2 blocks/SM.
// Heavy: lane quartet per pixel pair. lane = (q<<3)|p : quarter q owns
// channels [16q,16q+16), p indexes 8 pixel-pairs per warp. Thread handles
// pixels pxa = half*64 + w*8 + p and pxb = pxa+128. GEMM1 dots joined by
// shfl_xor(8) + shfl_xor(16) butterfly. Weight rows stored as 4 chunks of
// 16 floats at 20-float stride (16B aligned, conflict-free across quarters).
#define ROWP   80                  // padded row stride (floats)
#define CHK    20                  // per-quarter chunk stride
#define SM_W1  0                   // 128*80
#define SM_W2  10240               // 128*80
#define SM_B1  20480               // 128
#define SM_B2  20608               // 80
#define SM_WA  20688               // 80
#define SM_BA  20768
#define SMEM_FLOATS 20772
#define SMEM_BYTES (SMEM_FLOATS*4)

__global__ void __launch_bounds__(256, 2)
main_kernel(const float* __restrict__ x,
            const float* __restrict__ W2g, const float* __restrict__ b1,
            const float* __restrict__ b2, const float* __restrict__ Wa,
            const float* __restrict__ ba,
            float* __restrict__ out) {
    extern __shared__ float sm[];
    int blk  = blockIdx.x;
    int tile = blk >> 1;
    int half = blk & 1;
    int b    = tile >> 10;
    int k    = tile & (K_-1);
    int gh   = k >> 5, gw = k & 31;
    int t    = threadIdx.x;

    int tile_base = b*CHW_ + (gh*T_)*W_ + gw*T_;
    float* heavy = out + HEAVY_OFF;
    float* det   = out + DET_OFF;
    float* alp   = out + ALPHA_OFF;

    if (!g_sel[tile]) {
        // ---- cheap path: 128 px (rows [half*8, half*8+8)) ----
        int rbase = half*8;
        #pragma unroll 8
        for (int i = t; i < 2048; i += 256) {
            int c = i >> 5; int l = i & 31;
            int off = tile_base + c*HW_ + (rbase + (l >> 2))*W_ + (l & 3)*4;
            float4 v = *(const float4*)(x + off);
            *(float4*)(heavy + off) = v;
            *(float4*)(det   + off) = make_float4(0.f,0.f,0.f,0.f);
        }
        if (t < 32) {
            int aoff = b*HW_ + (gh*T_ + rbase + (t >> 2))*W_ + gw*T_ + (t & 3)*4;
            *(float4*)(alp + aoff) = make_float4(0.f,0.f,0.f,0.f);
        }
        return;
    }

    // ---- stage weights: 4 chunks of 16 floats per row, stride 20 ----
    for (int i = t; i < HID_*C_; i += 256) {
        int d = i >> 6, c = i & 63;
        int dst = d*ROWP + (c >> 4)*CHK + (c & 15);
        sm[SM_W1 + dst] = g_W1T[i];
        sm[SM_W2 + dst] = W2g[i];
    }
    if (t < HID_) sm[SM_B1 + t] = b1[t];
    if (t < C_) {
        int dst = (t >> 4)*CHK + (t & 15);
        sm[SM_B2 + dst] = b2[t];
        sm[SM_WA + dst] = Wa[t];
    }
    if (t == 0) sm[SM_BA] = ba[0];
    __syncthreads();

    int lane = t & 31;
    int q    = lane >> 3;                 // channel quarter 0..3
    int p    = lane & 7;                  // pixel-pair slot in warp
    int w    = t >> 5;
    int pxa  = half*64 + w*8 + p;         // 0..127 ; pxb = pxa+128
    int ra   = pxa >> 4, cpos = pxa & 15;
    int pbaseA = tile_base + ra*W_ + cpos;
    int pbaseB = pbaseA + 8*W_;
    int cbase  = q*16;
    int woff   = q*CHK;

    // x for both pixels, this thread's 16 channels, packed into 8 f32x2
    u64 xa2[8], xb2[8];
    #pragma unroll
    for (int j = 0; j < 8; ++j) {
        int o = (cbase + 2*j)*HW_;
        xa2[j] = pack2(x[pbaseA + o], x[pbaseA + o + HW_]);
        xb2[j] = pack2(x[pbaseB + o], x[pbaseB + o + HW_]);
    }

    // alpha for both pixels (quarter-dot + butterfly)
    float alphaA, alphaB;
    {
        const ulonglong2* war = (const ulonglong2*)(sm + SM_WA + woff);
        ulonglong2 w0 = war[0], w1 = war[1], w2v = war[2], w3 = war[3];
        u64 a0=0, a1=0, c0=0, c1=0;
        a0 = ffma2(xa2[0], w0.x, a0); a1 = ffma2(xa2[1], w0.y, a1);
        a0 = ffma2(xa2[2], w1.x, a0); a1 = ffma2(xa2[3], w1.y, a1);
        a0 = ffma2(xa2[4], w2v.x, a0); a1 = ffma2(xa2[5], w2v.y, a1);
        a0 = ffma2(xa2[6], w3.x, a0); a1 = ffma2(xa2[7], w3.y, a1);
        c0 = ffma2(xb2[0], w0.x, c0); c1 = ffma2(xb2[1], w0.y, c1);
        c0 = ffma2(xb2[2], w1.x, c0); c1 = ffma2(xb2[3], w1.y, c1);
        c0 = ffma2(xb2[4], w2v.x, c0); c1 = ffma2(xb2[5], w2v.y, c1);
        c0 = ffma2(xb2[6], w3.x, c0); c1 = ffma2(xb2[7], w3.y, c1);
        float pa = hsum2(add2(a0, a1));
        float pb = hsum2(add2(c0, c1));
        pa += __shfl_xor_sync(0xFFFFFFFFu, pa, 8);
        pa += __shfl_xor_sync(0xFFFFFFFFu, pa, 16);
        pb += __shfl_xor_sync(0xFFFFFFFFu, pb, 8);
        pb += __shfl_xor_sync(0xFFFFFFFFu, pb, 16);
        alphaA = fast_sigmoid(pa + sm[SM_BA]);
        alphaB = fast_sigmoid(pb + sm[SM_BA]);
    }

    // accumulators: 16 out-channels per pixel
    u64 acca[8], accb[8];
    #pragma unroll
    for (int j = 0; j < 8; ++j) {
        u64 bb = pack2(sm[SM_B2 + woff + 2*j], sm[SM_B2 + woff + 2*j + 1]);
        acca[j] = bb; accb[j] = bb;
    }

    const float* smW1 = sm + SM_W1 + woff;
    const float* smW2 = sm + SM_W2 + woff;

    for (int d = 0; d < HID_; d += 2) {
        const ulonglong2* w1r0 = (const ulonglong2*)(smW1 + d*ROWP);
        const ulonglong2* w1r1 = (const ulonglong2*)(smW1 + d*ROWP + ROWP);
        ulonglong2 p0 = w1r0[0], p1 = w1r0[1], p2 = w1r0[2], p3 = w1r0[3];
        ulonglong2 q0 = w1r1[0], q1 = w1r1[1], q2 = w1r1[2], q3 = w1r1[3];
        // 4 quarter-dots: rows {d,d+1} x px {a,b}
        u64 da0=0,da1=0, db0=0,db1=0, ea0=0,ea1=0, eb0=0,eb1=0;
        da0=ffma2(xa2[0],p0.x,da0); da1=ffma2(xa2[1],p0.y,da1);
        da0=ffma2(xa2[2],p1.x,da0); da1=ffma2(xa2[3],p1.y,da1);
        da0=ffma2(xa2[4],p2.x,da0); da1=ffma2(xa2[5],p2.y,da1);
        da0=ffma2(xa2[6],p3.x,da0); da1=ffma2(xa2[7],p3.y,da1);
        db0=ffma2(xb2[0],p0.x,db0); db1=ffma2(xb2[1],p0.y,db1);
        db0=ffma2(xb2[2],p1.x,db0); db1=ffma2(xb2[3],p1.y,db1);
        db0=ffma2(xb2[4],p2.x,db0); db1=ffma2(xb2[5],p2.y,db1);
        db0=ffma2(xb2[6],p3.x,db0); db1=ffma2(xb2[7],p3.y,db1);
        ea0=ffma2(xa2[0],q0.x,ea0); ea1=ffma2(xa2[1],q0.y,ea1);
        ea0=ffma2(xa2[2],q1.x,ea0); ea1=ffma2(xa2[3],q1.y,ea1);
        ea0=ffma2(xa2[4],q2.x,ea0); ea1=ffma2(xa2[5],q2.y,ea1);
        ea0=ffma2(xa2[6],q3.x,ea0); ea1=ffma2(xa2[7],q3.y,ea1);
        eb0=ffma2(xb2[0],q0.x,eb0); eb1=ffma2(xb2[1],q0.y,eb1);
        eb0=ffma2(xb2[2],q1.x,eb0); eb1=ffma2(xb2[3],q1.y,eb1);
        eb0=ffma2(xb2[4],q2.x,eb0); eb1=ffma2(xb2[5],q2.y,eb1);
        eb0=ffma2(xb2[6],q3.x,eb0); eb1=ffma2(xb2[7],q3.y,eb1);
        float rA0 = hsum2(add2(da0, da1));
        float rB0 = hsum2(add2(db0, db1));
        float rA1 = hsum2(add2(ea0, ea1));
        float rB1 = hsum2(add2(eb0, eb1));
        rA0 += __shfl_xor_sync(0xFFFFFFFFu, rA0, 8);
        rA0 += __shfl_xor_sync(0xFFFFFFFFu, rA0, 16);
        rB0 += __shfl_xor_sync(0xFFFFFFFFu, rB0, 8);
        rB0 += __shfl_xor_sync(0xFFFFFFFFu, rB0, 16);
        rA1 += __shfl_xor_sync(0xFFFFFFFFu, rA1, 8);
        rA1 += __shfl_xor_sync(0xFFFFFFFFu, rA1, 16);
        rB1 += __shfl_xor_sync(0xFFFFFFFFu, rB1, 8);
        rB1 += __shfl_xor_sync(0xFFFFFFFFu, rB1, 16);
        float bi0 = sm[SM_B1 + d], bi1 = sm[SM_B1 + d + 1];
        float hA0 = gelu_tanh(rA0 + bi0);
        float hB0 = gelu_tanh(rB0 + bi0);
        float hA1 = gelu_tanh(rA1 + bi1);
        float hB1 = gelu_tanh(rB1 + bi1);
        u64 hA02 = pack2(hA0, hA0), hA12 = pack2(hA1, hA1);
        u64 hB02 = pack2(hB0, hB0), hB12 = pack2(hB1, hB1);
        const ulonglong2* w2r0 = (const ulonglong2*)(smW2 + d*ROWP);
        const ulonglong2* w2r1 = (const ulonglong2*)(smW2 + d*ROWP + ROWP);
        ulonglong2 r0 = w2r0[0], r1 = w2r0[1], r2 = w2r0[2], r3 = w2r0[3];
        ulonglong2 s0 = w2r1[0], s1 = w2r1[1], s2 = w2r1[2], s3 = w2r1[3];
        acca[0] = ffma2(hA02, r0.x, acca[0]); acca[1] = ffma2(hA02, r0.y, acca[1]);
        acca[2] = ffma2(hA02, r1.x, acca[2]); acca[3] = ffma2(hA02, r1.y, acca[3]);
        acca[4] = ffma2(hA02, r2.x, acca[4]); acca[5] = ffma2(hA02, r2.y, acca[5]);
        acca[6] = ffma2(hA02, r3.x, acca[6]); acca[7] = ffma2(hA02, r3.y, acca[7]);
        acca[0] = ffma2(hA12, s0.x, acca[0]); acca[1] = ffma2(hA12, s0.y, acca[1]);
        acca[2] = ffma2(hA12, s1.x, acca[2]); acca[3] = ffma2(hA12, s1.y, acca[3]);
        acca[4] = ffma2(hA12, s2.x, acca[4]); acca[5] = ffma2(hA12, s2.y, acca[5]);
        acca[6] = ffma2(hA12, s3.x, acca[6]); acca[7] = ffma2(hA12, s3.y, acca[7]);
        accb[0] = ffma2(hB02, r0.x, accb[0]); accb[1] = ffma2(hB02, r0.y, accb[1]);
        accb[2] = ffma2(hB02, r1.x, accb[2]); accb[3] = ffma2(hB02, r1.y, accb[3]);
        accb[4] = ffma2(hB02, r2.x, accb[4]); accb[5] = ffma2(hB02, r2.y, accb[5]);
        accb[6] = ffma2(hB02, r3.x, accb[6]); accb[7] = ffma2(hB02, r3.y, accb[7]);
        accb[0] = ffma2(hB12, s0.x, accb[0]); accb[1] = ffma2(hB12, s0.y, accb[1]);
        accb[2] = ffma2(hB12, s1.x, accb[2]); accb[3] = ffma2(hB12, s1.y, accb[3]);
        accb[4] = ffma2(hB12, s2.x, accb[4]); accb[5] = ffma2(hB12, s2.y, accb[5]);
        accb[6] = ffma2(hB12, s3.x, accb[6]); accb[7] = ffma2(hB12, s3.y, accb[7]);
    }

    if (q == 0) {
        int arow = b*HW_ + (gh*T_ + ra)*W_ + gw*T_ + cpos;
        alp[arow] = alphaA;
        alp[arow + 8*W_] = alphaB;
    }
    #pragma unroll
    for (int j = 0; j < 8; ++j) {
        int o = (cbase + 2*j)*HW_;
        float d0, d1, x0, x1;
        unpack2(acca[j], d0, d1);
        unpack2(xa2[j],  x0, x1);
        det[pbaseA + o]        = d0;
        det[pbaseA + o + HW_]  = d1;
        heavy[pbaseA + o]       = fmaf(alphaA, d0, x0);
        heavy[pbaseA + o + HW_] = fmaf(alphaA, d1, x1);
        unpack2(accb[j], d0, d1);
        unpack2(xb2[j],  x0, x1);
        det[pbaseB + o]        = d0;
        det[pbaseB + o + HW_]  = d1;
        heavy[pbaseB + o]       = fmaf(alphaB, d0, x0);
        heavy[pbaseB + o + HW_] = fmaf(alphaB, d1, x1);
    }
}

// ---------------- launcher ----------------
extern "C" void kernel_launch(void* const* d_in, const int* in_sizes, int n_in,
                              void* d_out, int out_size) {
    const float* x  = (const float*)d_in[0];
    const float* u  = (const float*)d_in[1];
    const float* W1 = (const float*)d_in[2];
    const float* b1 = (const float*)d_in[3];
    const float* W2 = (const float*)d_in[4];
    const float* b2 = (const float*)d_in[5];
    const float* Wa = (const float*)d_in[6];
    const float* ba = (const float*)d_in[7];
    float* out = (float*)d_out;

    cudaFuncSetAttribute(main_kernel,
                         cudaFuncAttributeMaxDynamicSharedMemorySize, SMEM_BYTES);

    prep_kernel<<<34, 256>>>(u, W1, out);
    main_kernel<<<2*B_*K_, 256, SMEM_BYTES>>>(x, W2, b1, b2, Wa, ba, out);
}

// round 8
// speedup vs baseline: 1.0058x; 1.0006x over previous
#include <cuda_runtime.h>

// ---------------- problem constants ----------------
#define B_    2
#define C_    64
#define H_    512
#define W_    512
#define T_    16
#define K_    1024          // tiles per sample
#define KMAX_ 256
#define HID_  128
#define HW_   (H_*W_)       // 262144
#define CHW_  (C_*HW_)      // 16777216

// output layout (flatten-concat of the tuple, all f32)
#define HEAVY_OFF  0
#define DET_OFF    33554432
#define ALPHA_OFF  67108864
#define P_OFF      67633152
#define G_OFF      67635200
#define COST_OFF   67637248
#define BL_OFF     67637249

__device__ int   g_sel[B_*K_];
__device__ float g_W1T[HID_*C_];   // [d][c]

typedef unsigned long long u64;

// ---------------- packed f32x2 helpers ----------------
__device__ __forceinline__ u64 pack2(float lo, float hi) {
    u64 r; asm("mov.b64 %0, {%1, %2};" : "=l"(r) : "f"(lo), "f"(hi)); return r;
}
__device__ __forceinline__ void unpack2(u64 v, float& lo, float& hi) {
    asm("mov.b64 {%0, %1}, %2;" : "=f"(lo), "=f"(hi) : "l"(v));
}
__device__ __forceinline__ u64 ffma2(u64 a, u64 b, u64 c) {
    u64 d; asm("fma.rn.f32x2 %0, %1, %2, %3;" : "=l"(d) : "l"(a), "l"(b), "l"(c));
    return d;
}
__device__ __forceinline__ u64 add2(u64 a, u64 b) {
    u64 d; asm("add.rn.f32x2 %0, %1, %2;" : "=l"(d) : "l"(a), "l"(b));
    return d;
}
__device__ __forceinline__ float hsum2(u64 v) {
    float lo, hi; unpack2(v, lo, hi); return lo + hi;
}

// ---------------- math helpers ----------------
__device__ __forceinline__ float fast_sigmoid(float v) {
    return __fdividef(1.f, 1.f + __expf(-v));
}
__device__ __forceinline__ float gelu_tanh(float v) {
    float z  = 0.7978845608028654f * fmaf(0.044715f * v, v * v, v);
    float th; asm("tanh.approx.f32 %0, %1;" : "=f"(th) : "f"(z));
    return 0.5f * v * (1.f + th);
}

// ---------------- prep kernel: select (blk 0-31) + gate (32) + W1T (33) ----
__global__ void __launch_bounds__(256)
prep_kernel(const float* __restrict__ u, const float* __restrict__ W1,
            float* __restrict__ out) {
    __shared__ float sh[64*129];
    int blk = blockIdx.x;
    int t   = threadIdx.x;

    if (blk < 32) {
        float* us = sh;
        int b   = blk >> 4;
        int seg = blk & 15;
        for (int i = t; i < K_; i += 256) us[i] = u[b*K_ + i];
        __syncthreads();
        int e   = seg*64 + (t >> 2);
        int sub = t & 3;
        float ue = us[e];
        int cnt = 0;
        if (ue >= 0.f) {
            int j0 = sub * 256;
            #pragma unroll 4
            for (int j = j0; j < j0 + 256; ++j) {
                float uj = us[j];
                if (uj >= 0.f && (uj > ue || (uj == ue && j < e))) cnt++;
            }
        }
        cnt += __shfl_xor_sync(0xFFFFFFFFu, cnt, 1);
        cnt += __shfl_xor_sync(0xFFFFFFFFu, cnt, 2);
        if (sub == 0) g_sel[b*K_ + e] = (ue >= 0.f && cnt < KMAX_) ? 1 : 0;
    } else if (blk == 32) {
        float partial = 0.f;
        #pragma unroll
        for (int e = t; e < B_*K_; e += 256) {
            float uv = u[e];
            float p  = fast_sigmoid(uv);
            float hard = (uv >= 0.f) ? 1.f : 0.f;
            float gate = (hard + p) - p;
            out[P_OFF + e] = p;
            out[G_OFF + e] = gate;
            partial += fmaf(p, 0.9f, 0.1f);
        }
        #pragma unroll
        for (int s = 16; s > 0; s >>= 1)
            partial += __shfl_xor_sync(0xFFFFFFFFu, partial, s);
        if ((t & 31) == 0) sh[t >> 5] = partial;
        __syncthreads();
        if (t == 0) {
            float cost = 0.f;
            #pragma unroll
            for (int w = 0; w < 8; ++w) cost += sh[w];
            out[COST_OFF] = cost;
            float bl = cost - 1024.f;
            out[BL_OFF] = bl > 0.f ? bl : 0.f;
        }
    } else {
        for (int i = t; i < C_*HID_; i += 256) {
            int c = i >> 7, d = i & 127;
            sh[c*129 + d] = W1[i];
        }
        __syncthreads();
        for (int i = t; i < C_*HID_; i += 256) {
            int d = i >> 6, c = i & 63;
            g_W1T[i] = sh[c*129 + d];
        }
    }
}

// ---------------- main kernel ----------------
// grid = 2*B*K blocks (half-tile each), 256 threads, 2 blocks/SM.
// Heavy: lane quartet per pixel pair. lane = (q<<3)|p : quarter q owns
// channels [16q,16q+16), p indexes 8 pixel-pairs per warp. Thread handles
// pixels pxa = half*64 + w*8 + p and pxb = pxa+128. GEMM1 dots joined by
// shfl_xor(8) + shfl_xor(16) butterfly. Weight rows stored as 4 chunks of
// 16 floats at 20-float stride (16B aligned, conflict-free across quarters).
#define ROWP   80                  // padded row stride (floats)
#define CHK    20                  // per-quarter chunk stride
#define SM_W1  0                   // 128*80
#define SM_W2  10240               // 128*80
#define SM_B1  20480               // 128
#define SM_B2  20608               // 80
#define SM_WA  20688               // 80
#define SM_BA  20768
#define SMEM_FLOATS 20772
#define SMEM_BYTES (SMEM_FLOATS*4)

__global__ void __launch_bounds__(256, 2)
main_kernel(const float* __restrict__ x,
            const float* __restrict__ W2g, const float* __restrict__ b1,
            const float* __restrict__ b2, const float* __restrict__ Wa,
            const float* __restrict__ ba,
            float* __restrict__ out) {
    extern __shared__ float sm[];
    int blk  = blockIdx.x;
    int tile = blk >> 1;
    int half = blk & 1;
    int b    = tile >> 10;
    int k    = tile & (K_-1);
    int gh   = k >> 5, gw = k & 31;
    int t    = threadIdx.x;

    int tile_base = b*CHW_ + (gh*T_)*W_ + gw*T_;
    float* heavy = out + HEAVY_OFF;
    float* det   = out + DET_OFF;
    float* alp   = out + ALPHA_OFF;

    if (!g_sel[tile]) {
        // ---- cheap path: 128 px (rows [half*8, half*8+8)) ----
        int rbase = half*8;
        #pragma unroll 8
        for (int i = t; i < 2048; i += 256) {
            int c = i >> 5; int l = i & 31;
            int off = tile_base + c*HW_ + (rbase + (l >> 2))*W_ + (l & 3)*4;
            float4 v = *(const float4*)(x + off);
            *(float4*)(heavy + off) = v;
            *(float4*)(det   + off) = make_float4(0.f,0.f,0.f,0.f);
        }
        if (t < 32) {
            int aoff = b*HW_ + (gh*T_ + rbase + (t >> 2))*W_ + gw*T_ + (t & 3)*4;
            *(float4*)(alp + aoff) = make_float4(0.f,0.f,0.f,0.f);
        }
        return;
    }

    // ---- stage weights: 4 chunks of 16 floats per row, stride 20 ----
    for (int i = t; i < HID_*C_; i += 256) {
        int d = i >> 6, c = i & 63;
        int dst = d*ROWP + (c >> 4)*CHK + (c & 15);
        sm[SM_W1 + dst] = g_W1T[i];
        sm[SM_W2 + dst] = W2g[i];
    }
    if (t < HID_) sm[SM_B1 + t] = b1[t];
    if (t < C_) {
        int dst = (t >> 4)*CHK + (t & 15);
        sm[SM_B2 + dst] = b2[t];
        sm[SM_WA + dst] = Wa[t];
    }
    if (t == 0) sm[SM_BA] = ba[0];
    __syncthreads();

    int lane = t & 31;
    int q    = lane >> 3;                 // channel quarter 0..3
    int p    = lane & 7;                  // pixel-pair slot in warp
    int w    = t >> 5;
    int pxa  = half*64 + w*8 + p;         // 0..127 ; pxb = pxa+128
    int ra   = pxa >> 4, cpos = pxa & 15;
    int pbaseA = tile_base + ra*W_ + cpos;
    int pbaseB = pbaseA + 8*W_;
    int cbase  = q*16;
    int woff   = q*CHK;

    // x for both pixels, this thread's 16 channels, packed into 8 f32x2
    u64 xa2[8], xb2[8];
    #pragma unroll
    for (int j = 0; j < 8; ++j) {
        int o = (cbase + 2*j)*HW_;
        xa2[j] = pack2(x[pbaseA + o], x[pbaseA + o + HW_]);
        xb2[j] = pack2(x[pbaseB + o], x[pbaseB + o + HW_]);
    }

    // alpha for both pixels (quarter-dot + butterfly)
    float alphaA, alphaB;
    {
        const ulonglong2* war = (const ulonglong2*)(sm + SM_WA + woff);
        ulonglong2 w0 = war[0], w1 = war[1], w2v = war[2], w3 = war[3];
        u64 a0=0, a1=0, c0=0, c1=0;
        a0 = ffma2(xa2[0], w0.x, a0); a1 = ffma2(xa2[1], w0.y, a1);
        a0 = ffma2(xa2[2], w1.x, a0); a1 = ffma2(xa2[3], w1.y, a1);
        a0 = ffma2(xa2[4], w2v.x, a0); a1 = ffma2(xa2[5], w2v.y, a1);
        a0 = ffma2(xa2[6], w3.x, a0); a1 = ffma2(xa2[7], w3.y, a1);
        c0 = ffma2(xb2[0], w0.x, c0); c1 = ffma2(xb2[1], w0.y, c1);
        c0 = ffma2(xb2[2], w1.x, c0); c1 = ffma2(xb2[3], w1.y, c1);
        c0 = ffma2(xb2[4], w2v.x, c0); c1 = ffma2(xb2[5], w2v.y, c1);
        c0 = ffma2(xb2[6], w3.x, c0); c1 = ffma2(xb2[7], w3.y, c1);
        float pa = hsum2(add2(a0, a1));
        float pb = hsum2(add2(c0, c1));
        pa += __shfl_xor_sync(0xFFFFFFFFu, pa, 8);
        pa += __shfl_xor_sync(0xFFFFFFFFu, pa, 16);
        pb += __shfl_xor_sync(0xFFFFFFFFu, pb, 8);
        pb += __shfl_xor_sync(0xFFFFFFFFu, pb, 16);
        alphaA = fast_sigmoid(pa + sm[SM_BA]);
        alphaB = fast_sigmoid(pb + sm[SM_BA]);
    }

    // accumulators: 16 out-channels per pixel
    u64 acca[8], accb[8];
    #pragma unroll
    for (int j = 0; j < 8; ++j) {
        u64 bb = pack2(sm[SM_B2 + woff + 2*j], sm[SM_B2 + woff + 2*j + 1]);
        acca[j] = bb; accb[j] = bb;
    }

    const float* smW1 = sm + SM_W1 + woff;
    const float* smW2 = sm + SM_W2 + woff;

    for (int d = 0; d < HID_; d += 2) {
        const ulonglong2* w1r0 = (const ulonglong2*)(smW1 + d*ROWP);
        const ulonglong2* w1r1 = (const ulonglong2*)(smW1 + d*ROWP + ROWP);
        ulonglong2 p0 = w1r0[0], p1 = w1r0[1], p2 = w1r0[2], p3 = w1r0[3];
        ulonglong2 q0 = w1r1[0], q1 = w1r1[1], q2 = w1r1[2], q3 = w1r1[3];
        // 4 quarter-dots: rows {d,d+1} x px {a,b}
        u64 da0=0,da1=0, db0=0,db1=0, ea0=0,ea1=0, eb0=0,eb1=0;
        da0=ffma2(xa2[0],p0.x,da0); da1=ffma2(xa2[1],p0.y,da1);
        da0=ffma2(xa2[2],p1.x,da0); da1=ffma2(xa2[3],p1.y,da1);
        da0=ffma2(xa2[4],p2.x,da0); da1=ffma2(xa2[5],p2.y,da1);
        da0=ffma2(xa2[6],p3.x,da0); da1=ffma2(xa2[7],p3.y,da1);
        db0=ffma2(xb2[0],p0.x,db0); db1=ffma2(xb2[1],p0.y,db1);
        db0=ffma2(xb2[2],p1.x,db0); db1=ffma2(xb2[3],p1.y,db1);
        db0=ffma2(xb2[4],p2.x,db0); db1=ffma2(xb2[5],p2.y,db1);
        db0=ffma2(xb2[6],p3.x,db0); db1=ffma2(xb2[7],p3.y,db1);
        ea0=ffma2(xa2[0],q0.x,ea0); ea1=ffma2(xa2[1],q0.y,ea1);
        ea0=ffma2(xa2[2],q1.x,ea0); ea1=ffma2(xa2[3],q1.y,ea1);
        ea0=ffma2(xa2[4],q2.x,ea0); ea1=ffma2(xa2[5],q2.y,ea1);
        ea0=ffma2(xa2[6],q3.x,ea0); ea1=ffma2(xa2[7],q3.y,ea1);
        eb0=ffma2(xb2[0],q0.x,eb0); eb1=ffma2(xb2[1],q0.y,eb1);
        eb0=ffma2(xb2[2],q1.x,eb0); eb1=ffma2(xb2[3],q1.y,eb1);
        eb0=ffma2(xb2[4],q2.x,eb0); eb1=ffma2(xb2[5],q2.y,eb1);
        eb0=ffma2(xb2[6],q3.x,eb0); eb1=ffma2(xb2[7],q3.y,eb1);
        float rA0 = hsum2(add2(da0, da1));
        float rB0 = hsum2(add2(db0, db1));
        float rA1 = hsum2(add2(ea0, ea1));
        float rB1 = hsum2(add2(eb0, eb1));
        rA0 += __shfl_xor_sync(0xFFFFFFFFu, rA0, 8);
        rA0 += __shfl_xor_sync(0xFFFFFFFFu, rA0, 16);
        rB0 += __shfl_xor_sync(0xFFFFFFFFu, rB0, 8);
        rB0 += __shfl_xor_sync(0xFFFFFFFFu, rB0, 16);
        rA1 += __shfl_xor_sync(0xFFFFFFFFu, rA1, 8);
        rA1 += __shfl_xor_sync(0xFFFFFFFFu, rA1, 16);
        rB1 += __shfl_xor_sync(0xFFFFFFFFu, rB1, 8);
        rB1 += __shfl_xor_sync(0xFFFFFFFFu, rB1, 16);
        float bi0 = sm[SM_B1 + d], bi1 = sm[SM_B1 + d + 1];
        float hA0 = gelu_tanh(rA0 + bi0);
        float hB0 = gelu_tanh(rB0 + bi0);
        float hA1 = gelu_tanh(rA1 + bi1);
        float hB1 = gelu_tanh(rB1 + bi1);
        u64 hA02 = pack2(hA0, hA0), hA12 = pack2(hA1, hA1);
        u64 hB02 = pack2(hB0, hB0), hB12 = pack2(hB1, hB1);
        const ulonglong2* w2r0 = (const ulonglong2*)(smW2 + d*ROWP);
        const ulonglong2* w2r1 = (const ulonglong2*)(smW2 + d*ROWP + ROWP);
        ulonglong2 r0 = w2r0[0], r1 = w2r0[1], r2 = w2r0[2], r3 = w2r0[3];
        ulonglong2 s0 = w2r1[0], s1 = w2r1[1], s2 = w2r1[2], s3 = w2r1[3];
        acca[0] = ffma2(hA02, r0.x, acca[0]); acca[1] = ffma2(hA02, r0.y, acca[1]);
        acca[2] = ffma2(hA02, r1.x, acca[2]); acca[3] = ffma2(hA02, r1.y, acca[3]);
        acca[4] = ffma2(hA02, r2.x, acca[4]); acca[5] = ffma2(hA02, r2.y, acca[5]);
        acca[6] = ffma2(hA02, r3.x, acca[6]); acca[7] = ffma2(hA02, r3.y, acca[7]);
        acca[0] = ffma2(hA12, s0.x, acca[0]); acca[1] = ffma2(hA12, s0.y, acca[1]);
        acca[2] = ffma2(hA12, s1.x, acca[2]); acca[3] = ffma2(hA12, s1.y, acca[3]);
        acca[4] = ffma2(hA12, s2.x, acca[4]); acca[5] = ffma2(hA12, s2.y, acca[5]);
        acca[6] = ffma2(hA12, s3.x, acca[6]); acca[7] = ffma2(hA12, s3.y, acca[7]);
        accb[0] = ffma2(hB02, r0.x, accb[0]); accb[1] = ffma2(hB02, r0.y, accb[1]);
        accb[2] = ffma2(hB02, r1.x, accb[2]); accb[3] = ffma2(hB02, r1.y, accb[3]);
        accb[4] = ffma2(hB02, r2.x, accb[4]); accb[5] = ffma2(hB02, r2.y, accb[5]);
        accb[6] = ffma2(hB02, r3.x, accb[6]); accb[7] = ffma2(hB02, r3.y, accb[7]);
        accb[0] = ffma2(hB12, s0.x, accb[0]); accb[1] = ffma2(hB12, s0.y, accb[1]);
        accb[2] = ffma2(hB12, s1.x, accb[2]); accb[3] = ffma2(hB12, s1.y, accb[3]);
        accb[4] = ffma2(hB12, s2.x, accb[4]); accb[5] = ffma2(hB12, s2.y, accb[5]);
        accb[6] = ffma2(hB12, s3.x, accb[6]); accb[7] = ffma2(hB12, s3.y, accb[7]);
    }

    if (q == 0) {
        int arow = b*HW_ + (gh*T_ + ra)*W_ + gw*T_ + cpos;
        alp[arow] = alphaA;
        alp[arow + 8*W_] = alphaB;
    }
    #pragma unroll
    for (int j = 0; j < 8; ++j) {
        int o = (cbase + 2*j)*HW_;
        float d0, d1, x0, x1;
        unpack2(acca[j], d0, d1);
        unpack2(xa2[j],  x0, x1);
        det[pbaseA + o]        = d0;
        det[pbaseA + o + HW_]  = d1;
        heavy[pbaseA + o]       = fmaf(alphaA, d0, x0);
        heavy[pbaseA + o + HW_] = fmaf(alphaA, d1, x1);
        unpack2(accb[j], d0, d1);
        unpack2(xb2[j],  x0, x1);
        det[pbaseB + o]        = d0;
        det[pbaseB + o + HW_]  = d1;
        heavy[pbaseB + o]       = fmaf(alphaB, d0, x0);
        heavy[pbaseB + o + HW_] = fmaf(alphaB, d1, x1);
    }
}

// ---------------- launcher ----------------
extern "C" void kernel_launch(void* const* d_in, const int* in_sizes, int n_in,
                              void* d_out, int out_size) {
    const float* x  = (const float*)d_in[0];
    const float* u  = (const float*)d_in[1];
    const float* W1 = (const float*)d_in[2];
    const float* b1 = (const float*)d_in[3];
    const float* W2 = (const float*)d_in[4];
    const float* b2 = (const float*)d_in[5];
    const float* Wa = (const float*)d_in[6];
    const float* ba = (const float*)d_in[7];
    float* out = (float*)d_out;

    cudaFuncSetAttribute(main_kernel,
                         cudaFuncAttributeMaxDynamicSharedMemorySize, SMEM_BYTES);

    prep_kernel<<<34, 256>>>(u, W1, out);
    main_kernel<<<2*B_*K_, 256, SMEM_BYTES>>>(x, W2, b1, b2, Wa, ba, out);
}

// round 9
// speedup vs baseline: 1.0603x; 1.0542x over previous
#include <cuda_runtime.h>

// ---------------- problem constants ----------------
#define B_    2
#define C_    64
#define H_    512
#define W_    512
#define T_    16
#define K_    1024
#define KMAX_ 256
#define HID_  128
#define HW_   (H_*W_)
#define CHW_  (C_*HW_)

// output layout (flatten-concat, all f32)
#define HEAVY_OFF  0
#define DET_OFF    33554432
#define ALPHA_OFF  67108864
#define P_OFF      67633152
#define G_OFF      67635200
#define COST_OFF   67637248
#define BL_OFF     67637249

__device__ int g_sel[B_*K_];

typedef unsigned long long u64;

// ---------------- packed f32x2 helpers ----------------
__device__ __forceinline__ u64 pack2(float lo, float hi) {
    u64 r; asm("mov.b64 %0, {%1, %2};" : "=l"(r) : "f"(lo), "f"(hi)); return r;
}
__device__ __forceinline__ void unpack2(u64 v, float& lo, float& hi) {
    asm("mov.b64 {%0, %1}, %2;" : "=f"(lo), "=f"(hi) : "l"(v));
}
__device__ __forceinline__ u64 ffma2(u64 a, u64 b, u64 c) {
    u64 d; asm("fma.rn.f32x2 %0, %1, %2, %3;" : "=l"(d) : "l"(a), "l"(b), "l"(c));
    return d;
}
__device__ __forceinline__ u64 add2(u64 a, u64 b) {
    u64 d; asm("add.rn.f32x2 %0, %1, %2;" : "=l"(d) : "l"(a), "l"(b));
    return d;
}

// ---------------- math helpers ----------------
__device__ __forceinline__ float fast_sigmoid(float v) {
    return __fdividef(1.f, 1.f + __expf(-v));
}
__device__ __forceinline__ float gelu_tanh(float v) {
    float z  = 0.7978845608028654f * fmaf(0.044715f * v, v * v, v);
    float th; asm("tanh.approx.f32 %0, %1;" : "=f"(th) : "f"(z));
    return 0.5f * v * (1.f + th);
}

// ---------------- prep kernel: select (blk 0-31) + gate (32) ----------------
__global__ void __launch_bounds__(256)
prep_kernel(const float* __restrict__ u, float* __restrict__ out) {
    __shared__ float sh[K_];
    int blk = blockIdx.x;
    int t   = threadIdx.x;

    if (blk < 32) {
        int b   = blk >> 4;
        int seg = blk & 15;
        for (int i = t; i < K_; i += 256) sh[i] = u[b*K_ + i];
        __syncthreads();
        int e   = seg*64 + (t >> 2);
        int sub = t & 3;
        float ue = sh[e];
        int cnt = 0;
        if (ue >= 0.f) {
            int j0 = sub * 256;
            #pragma unroll 4
            for (int j = j0; j < j0 + 256; ++j) {
                float uj = sh[j];
                if (uj >= 0.f && (uj > ue || (uj == ue && j < e))) cnt++;
            }
        }
        cnt += __shfl_xor_sync(0xFFFFFFFFu, cnt, 1);
        cnt += __shfl_xor_sync(0xFFFFFFFFu, cnt, 2);
        if (sub == 0) g_sel[b*K_ + e] = (ue >= 0.f && cnt < KMAX_) ? 1 : 0;
    } else {
        float partial = 0.f;
        #pragma unroll
        for (int e = t; e < B_*K_; e += 256) {
            float uv = u[e];
            float p  = fast_sigmoid(uv);
            float hard = (uv >= 0.f) ? 1.f : 0.f;
            float gate = (hard + p) - p;
            out[P_OFF + e] = p;
            out[G_OFF + e] = gate;
            partial += fmaf(p, 0.9f, 0.1f);
        }
        #pragma unroll
        for (int s = 16; s > 0; s >>= 1)
            partial += __shfl_xor_sync(0xFFFFFFFFu, partial, s);
        if ((t & 31) == 0) sh[t >> 5] = partial;
        __syncthreads();
        if (t == 0) {
            float cost = 0.f;
            #pragma unroll
            for (int w = 0; w < 8; ++w) cost += sh[w];
            out[COST_OFF] = cost;
            float bl = cost - 1024.f;
            out[BL_OFF] = bl > 0.f ? bl : 0.f;
        }
    }
}

// ---------------- main kernel ----------------
// grid = 2*B*K (half-tile = 128 px per block), 256 threads, 2 blocks/SM.
// Two-phase SMEM GEMM in 2 chunks of 64 hidden dims:
//   GEMM1: thread tile 16d x 2px; w broadcast LDS.128 (natural d-pair f32x2),
//          x one LDS.64 + splat. 16 independent FFMA2 chains, no shuffles.
//   gelu batched 32-wide, h -> SMEM [d][px].
//   GEMM2: thread tile 16c x 2px, persistent f32x2 accumulators.
#define XS_   0        // x   [64c][128px]   8192 floats
#define W1C_  8192     // W1  [64c][64d]     4096
#define W2C_  12288    // W2  [64d][64c]     4096
#define HS_   16384    // h   [64d][128px]   8192
#define B1S_  24576    // 128
#define B2S_  24704    // 64
#define WAS_  24768    // 64
#define BAS_  24832    // 1 (+pad)
#define SMEM_FLOATS 24836
#define SMEM_BYTES  (SMEM_FLOATS*4)

__global__ void __launch_bounds__(256, 2)
main_kernel(const float* __restrict__ x,  const float* __restrict__ W1,
            const float* __restrict__ W2, const float* __restrict__ b1,
            const float* __restrict__ b2, const float* __restrict__ Wa,
            const float* __restrict__ ba, float* __restrict__ out) {
    extern __shared__ float sm[];
    const int blk  = blockIdx.x;
    const int tile = blk >> 1;
    const int half = blk & 1;
    const int b    = tile >> 10;
    const int k    = tile & (K_-1);
    const int gh   = k >> 5, gw = k & 31;
    const int t    = threadIdx.x;

    const int tile_base = b*CHW_ + (gh*T_)*W_ + gw*T_;
    const int rbase = half*8;
    float* heavy = out + HEAVY_OFF;
    float* det   = out + DET_OFF;
    float* alp   = out + ALPHA_OFF;

    if (!g_sel[tile]) {
        // ---- cheap path: heavy = x, detail = 0, alpha = 0 (128 px) ----
        #pragma unroll 8
        for (int i = t; i < 2048; i += 256) {
            int c = i >> 5; int l = i & 31;
            int off = tile_base + c*HW_ + (rbase + (l >> 2))*W_ + (l & 3)*4;
            float4 v = *(const float4*)(x + off);
            *(float4*)(heavy + off) = v;
            *(float4*)(det   + off) = make_float4(0.f,0.f,0.f,0.f);
        }
        if (t < 32) {
            int aoff = b*HW_ + (gh*T_ + rbase + (t >> 2))*W_ + gw*T_ + (t & 3)*4;
            *(float4*)(alp + aoff) = make_float4(0.f,0.f,0.f,0.f);
        }
        return;
    }

    float* xs  = sm + XS_;
    float* w1c = sm + W1C_;
    float* w2c = sm + W2C_;
    float* hs  = sm + HS_;
    float* b1s = sm + B1S_;
    float* b2s = sm + B2S_;
    float* was = sm + WAS_;

    // ---- prologue staging: x half-tile, W chunk 0, biases ----
    #pragma unroll
    for (int i = t; i < 2048; i += 256) {              // x tile
        int c = i >> 5, l = i & 31;
        *(float4*)(xs + c*128 + l*4) =
            *(const float4*)(x + tile_base + c*HW_ + (rbase + (l >> 2))*W_ + (l & 3)*4);
    }
    #pragma unroll
    for (int i = t; i < 1024; i += 256) {              // W1/W2 chunk 0
        int c = i >> 4, dq = i & 15;
        *(float4*)(w1c + c*64 + dq*4) = *(const float4*)(W1 + c*HID_ + dq*4);
        *(float4*)(w2c + i*4)         = *(const float4*)(W2 + i*4);
    }
    if (t < HID_) b1s[t] = b1[t];
    if (t < C_)  { b2s[t] = b2[t]; was[t] = Wa[t]; }
    if (t == 0)   sm[BAS_] = ba[0];
    __syncthreads();                                   // S1

    const int grp = t >> 6;            // d-group / c-group (0..3)
    const int pxp = t & 63;            // pixel pair
    const int px0 = 2*pxp;
    const int d0  = grp*16;            // within-chunk d offset
    const int c0  = grp*16;            // output channel offset
    const int r_loc = px0 >> 4, col = px0 & 15;
    const int pbase = tile_base + (rbase + r_loc)*W_ + col;

    // ---- alpha for the pixel pair ----
    float alphaL, alphaR;
    {
        u64 av = 0;
        #pragma unroll 8
        for (int c = 0; c < C_; ++c) {
            u64 xv = *(const u64*)(xs + c*128 + px0);
            float wv = was[c];
            av = ffma2(xv, pack2(wv, wv), av);
        }
        float sL, sR; unpack2(av, sL, sR);
        float bav = sm[BAS_];
        alphaL = fast_sigmoid(sL + bav);
        alphaR = fast_sigmoid(sR + bav);
    }

    // persistent GEMM2 accumulators (16 c x 2 px), init = b2
    u64 oL2[8], oR2[8];
    {
        const u64* b2v = (const u64*)(b2s + c0);
        #pragma unroll
        for (int j = 0; j < 8; ++j) { oL2[j] = b2v[j]; oR2[j] = b2v[j]; }
    }

    for (int ck = 0; ck < 2; ++ck) {
        if (ck) {
            __syncthreads();                           // S3: GEMM2 ck0 done
            #pragma unroll
            for (int i = t; i < 1024; i += 256) {      // stage chunk 1 weights
                int c = i >> 4, dq = i & 15;
                *(float4*)(w1c + c*64 + dq*4) =
                    *(const float4*)(W1 + c*HID_ + 64 + dq*4);
                *(float4*)(w2c + i*4) = *(const float4*)(W2 + 4096 + i*4);
            }
            __syncthreads();                           // S4
        }

        // ---- GEMM1: h_part[16d][2px] = x . W1chunk ----
        u64 aL2[8], aR2[8];
        #pragma unroll
        for (int j = 0; j < 8; ++j) { aL2[j] = 0; aR2[j] = 0; }

        #pragma unroll 4
        for (int c = 0; c < C_; ++c) {
            const ulonglong2* wr = (const ulonglong2*)(w1c + c*64 + d0);
            ulonglong2 w0 = wr[0], w1v = wr[1], w2v = wr[2], w3v = wr[3];
            u64 xv = *(const u64*)(xs + c*128 + px0);
            float xl, xh; unpack2(xv, xl, xh);
            u64 xL = pack2(xl, xl), xR = pack2(xh, xh);
            aL2[0] = ffma2(xL, w0.x,  aL2[0]);
            aL2[1] = ffma2(xL, w0.y,  aL2[1]);
            aL2[2] = ffma2(xL, w1v.x, aL2[2]);
            aL2[3] = ffma2(xL, w1v.y, aL2[3]);
            aL2[4] = ffma2(xL, w2v.x, aL2[4]);
            aL2[5] = ffma2(xL, w2v.y, aL2[5]);
            aL2[6] = ffma2(xL, w3v.x, aL2[6]);
            aL2[7] = ffma2(xL, w3v.y, aL2[7]);
            aR2[0] = ffma2(xR, w0.x,  aR2[0]);
            aR2[1] = ffma2(xR, w0.y,  aR2[1]);
            aR2[2] = ffma2(xR, w1v.x, aR2[2]);
            aR2[3] = ffma2(xR, w1v.y, aR2[3]);
            aR2[4] = ffma2(xR, w2v.x, aR2[4]);
            aR2[5] = ffma2(xR, w2v.y, aR2[5]);
            aR2[6] = ffma2(xR, w3v.x, aR2[6]);
            aR2[7] = ffma2(xR, w3v.y, aR2[7]);
        }

        // ---- bias + gelu (batched) + h -> SMEM ----
        {
            const u64* b1v = (const u64*)(b1s + ck*64 + d0);
            #pragma unroll
            for (int j = 0; j < 8; ++j) {
                float p0, p1, q0, q1;
                unpack2(add2(aL2[j], b1v[j]), p0, p1);
                unpack2(add2(aR2[j], b1v[j]), q0, q1);
                float g00 = gelu_tanh(p0), g01 = gelu_tanh(p1);
                float g10 = gelu_tanh(q0), g11 = gelu_tanh(q1);
                *(u64*)(hs + (d0 + 2*j    )*128 + px0) = pack2(g00, g10);
                *(u64*)(hs + (d0 + 2*j + 1)*128 + px0) = pack2(g01, g11);
            }
        }
        __syncthreads();                               // S2 / S5

        // ---- GEMM2: out[16c][2px] += h . W2chunk ----
        #pragma unroll 4
        for (int dl = 0; dl < 64; ++dl) {
            const ulonglong2* wr = (const ulonglong2*)(w2c + dl*64 + c0);
            ulonglong2 w0 = wr[0], w1v = wr[1], w2v = wr[2], w3v = wr[3];
            u64 hv = *(const u64*)(hs + dl*128 + px0);
            float hl, hh; unpack2(hv, hl, hh);
            u64 hL = pack2(hl, hl), hR = pack2(hh, hh);
            oL2[0] = ffma2(hL, w0.x,  oL2[0]);
            oL2[1] = ffma2(hL, w0.y,  oL2[1]);
            oL2[2] = ffma2(hL, w1v.x, oL2[2]);
            oL2[3] = ffma2(hL, w1v.y, oL2[3]);
            oL2[4] = ffma2(hL, w2v.x, oL2[4]);
            oL2[5] = ffma2(hL, w2v.y, oL2[5]);
            oL2[6] = ffma2(hL, w3v.x, oL2[6]);
            oL2[7] = ffma2(hL, w3v.y, oL2[7]);
            oR2[0] = ffma2(hR, w0.x,  oR2[0]);
            oR2[1] = ffma2(hR, w0.y,  oR2[1]);
            oR2[2] = ffma2(hR, w1v.x, oR2[2]);
            oR2[3] = ffma2(hR, w1v.y, oR2[3]);
            oR2[4] = ffma2(hR, w2v.x, oR2[4]);
            oR2[5] = ffma2(hR, w2v.y, oR2[5]);
            oR2[6] = ffma2(hR, w3v.x, oR2[6]);
            oR2[7] = ffma2(hR, w3v.y, oR2[7]);
        }
    }

    // ---- epilogue ----
    if (grp == 0) {
        int aoff = b*HW_ + (gh*T_ + rbase + r_loc)*W_ + gw*T_ + col;
        *(u64*)(alp + aoff) = pack2(alphaL, alphaR);
    }
    u64 al2 = pack2(alphaL, alphaR);
    #pragma unroll
    for (int j = 0; j < 8; ++j) {
        int c = c0 + 2*j;
        float dA0, dA1, dB0, dB1;
        unpack2(oL2[j], dA0, dA1);     // (c, c+1) @ px0
        unpack2(oR2[j], dB0, dB1);     // (c, c+1) @ px1
        u64 det0 = pack2(dA0, dB0);    // c   : (px0, px1)
        u64 det1 = pack2(dA1, dB1);    // c+1 : (px0, px1)
        int off0 = pbase + c*HW_;
        *(u64*)(det + off0)       = det0;
        *(u64*)(det + off0 + HW_) = det1;
        u64 xv0 = *(const u64*)(xs + c*128 + px0);
        u64 xv1 = *(const u64*)(xs + (c+1)*128 + px0);
        *(u64*)(heavy + off0)       = ffma2(al2, det0, xv0);
        *(u64*)(heavy + off0 + HW_) = ffma2(al2, det1, xv1);
    }
}

// ---------------- launcher ----------------
extern "C" void kernel_launch(void* const* d_in, const int* in_sizes, int n_in,
                              void* d_out, int out_size) {
    const float* x  = (const float*)d_in[0];
    const float* u  = (const float*)d_in[1];
    const float* W1 = (const float*)d_in[2];
    const float* b1 = (const float*)d_in[3];
    const float* W2 = (const float*)d_in[4];
    const float* b2 = (const float*)d_in[5];
    const float* Wa = (const float*)d_in[6];
    const float* ba = (const float*)d_in[7];
    float* out = (float*)d_out;

    cudaFuncSetAttribute(main_kernel,
                         cudaFuncAttributeMaxDynamicSharedMemorySize, SMEM_BYTES);

    prep_kernel<<<33, 256>>>(u, out);
    main_kernel<<<2*B_*K_, 256, SMEM_BYTES>>>(x, W1, W2, b1, b2, Wa, ba, out);
}

// round 12
// speedup vs baseline: 1.4595x; 1.3765x over previous
#include <cuda_runtime.h>

// ---------------- problem constants ----------------
#define B_    2
#define C_    64
#define H_    512
#define W_    512
#define T_    16
#define K_    1024
#define KMAX_ 256
#define HID_  128
#define HW_   (H_*W_)
#define CHW_  (C_*HW_)

// output layout (flatten-concat, all f32)
#define HEAVY_OFF  0
#define DET_OFF    33554432
#define ALPHA_OFF  67108864
#define P_OFF      67633152
#define G_OFF      67635200
#define COST_OFF   67637248
#define BL_OFF     67637249

typedef unsigned int u32;
typedef unsigned long long u64;

__device__ int g_sel[B_*K_];
__device__ u32 g_W1hi[4096], g_W1lo[4096];   // [c=64][d-pair=64]  bf16x2
__device__ u32 g_W2hi[4096], g_W2lo[4096];   // [d=128][c-pair=32] bf16x2

// ---------------- helpers ----------------
__device__ __forceinline__ u32 smem_u32(const void* p) {
    u32 a;
    asm("{ .reg .u64 t; cvta.to.shared.u64 t, %1; cvt.u32.u64 %0, t; }"
        : "=r"(a) : "l"(p));
    return a;
}
__device__ __forceinline__ float fast_sigmoid(float v) {
    return __fdividef(1.f, 1.f + __expf(-v));
}
__device__ __forceinline__ float gelu_tanh(float v) {
    float z  = 0.7978845608028654f * fmaf(0.044715f * v, v * v, v);
    float th; asm("tanh.approx.f32 %0, %1;" : "=f"(th) : "f"(z));
    return 0.5f * v * (1.f + th);
}
// split (v0,v1) into packed bf16x2 hi and lo (v ~= hi + lo)
__device__ __forceinline__ void split2(float v0, float v1, u32& hi, u32& lo) {
    u32 h; asm("cvt.rn.bf16x2.f32 %0, %1, %2;" : "=r"(h) : "f"(v1), "f"(v0));
    float f0 = __uint_as_float(h << 16);
    float f1 = __uint_as_float(h & 0xFFFF0000u);
    u32 l; asm("cvt.rn.bf16x2.f32 %0, %1, %2;" : "=r"(l) : "f"(v1 - f1), "f"(v0 - f0));
    hi = h; lo = l;
}
__device__ __forceinline__ float bf_lo(u32 v) { return __uint_as_float(v << 16); }
__device__ __forceinline__ float bf_hi(u32 v) { return __uint_as_float(v & 0xFFFF0000u); }

__device__ __forceinline__ void ldsm4(u32* r, u32 a) {
    asm volatile("ldmatrix.sync.aligned.m8n8.x4.shared.b16 {%0,%1,%2,%3}, [%4];"
        : "=r"(r[0]), "=r"(r[1]), "=r"(r[2]), "=r"(r[3]) : "r"(a));
}
__device__ __forceinline__ void ldsm4t(u32* r, u32 a) {
    asm volatile("ldmatrix.sync.aligned.m8n8.x4.trans.shared.b16 {%0,%1,%2,%3}, [%4];"
        : "=r"(r[0]), "=r"(r[1]), "=r"(r[2]), "=r"(r[3]) : "r"(a));
}
__device__ __forceinline__ void mma16816(float* d, const u32* a, u32 b0, u32 b1) {
    asm volatile(
        "mma.sync.aligned.m16n8k16.row.col.f32.bf16.bf16.f32 "
        "{%0,%1,%2,%3}, {%4,%5,%6,%7}, {%8,%9}, {%0,%1,%2,%3};"
        : "+f"(d[0]), "+f"(d[1]), "+f"(d[2]), "+f"(d[3])
        : "r"(a[0]), "r"(a[1]), "r"(a[2]), "r"(a[3]), "r"(b0), "r"(b1));
}

// ---------------- prep kernel ----------------
// blk 0-31: selection; 32: gate/cost; 33: W1 bf16-split; 34: W2 bf16-split
__global__ void __launch_bounds__(256)
prep_kernel(const float* __restrict__ u, const float* __restrict__ W1,
            const float* __restrict__ W2, float* __restrict__ out) {
    __shared__ float sh[K_];
    int blk = blockIdx.x;
    int t   = threadIdx.x;

    if (blk < 32) {
        int b   = blk >> 4;
        int seg = blk & 15;
        for (int i = t; i < K_; i += 256) sh[i] = u[b*K_ + i];
        __syncthreads();
        int e   = seg*64 + (t >> 2);
        int sub = t & 3;
        float ue = sh[e];
        int cnt = 0;
        if (ue >= 0.f) {
            int j0 = sub * 256;
            #pragma unroll 4
            for (int j = j0; j < j0 + 256; ++j) {
                float uj = sh[j];
                if (uj >= 0.f && (uj > ue || (uj == ue && j < e))) cnt++;
            }
        }
        cnt += __shfl_xor_sync(0xFFFFFFFFu, cnt, 1);
        cnt += __shfl_xor_sync(0xFFFFFFFFu, cnt, 2);
        if (sub == 0) g_sel[b*K_ + e] = (ue >= 0.f && cnt < KMAX_) ? 1 : 0;
    } else if (blk == 32) {
        float partial = 0.f;
        #pragma unroll
        for (int e = t; e < B_*K_; e += 256) {
            float uv = u[e];
            float p  = fast_sigmoid(uv);
            float hard = (uv >= 0.f) ? 1.f : 0.f;
            float gate = (hard + p) - p;
            out[P_OFF + e] = p;
            out[G_OFF + e] = gate;
            partial += fmaf(p, 0.9f, 0.1f);
        }
        #pragma unroll
        for (int s = 16; s > 0; s >>= 1)
            partial += __shfl_xor_sync(0xFFFFFFFFu, partial, s);
        if ((t & 31) == 0) sh[t >> 5] = partial;
        __syncthreads();
        if (t == 0) {
            float cost = 0.f;
            #pragma unroll
            for (int w = 0; w < 8; ++w) cost += sh[w];
            out[COST_OFF] = cost;
            float bl = cost - 1024.f;
            out[BL_OFF] = bl > 0.f ? bl : 0.f;
        }
    } else if (blk == 33) {
        // W1 [c=64][d=128] -> bf16 hi/lo, d-pairs packed
        for (int i = t; i < 4096; i += 256) {
            float2 v = *(const float2*)(W1 + 2*i);
            split2(v.x, v.y, g_W1hi[i], g_W1lo[i]);
        }
    } else {
        // W2 [d=128][c=64] -> bf16 hi/lo, c-pairs packed
        for (int i = t; i < 4096; i += 256) {
            float2 v = *(const float2*)(W2 + 2*i);
            split2(v.x, v.y, g_W2hi[i], g_W2lo[i]);
        }
    }
}

// ---------------- SMEM layout (byte offsets) ----------------
// pitches: X,W2 rows 144B (9 chunks); W1 rows 272B (17 chunks) — conflict-free
#define XHI_   0        // [128px][64c] bf16, pitch 144   -> 18432
#define XLO_   18432
#define W1HI_  36864    // [64c][128d] bf16, pitch 272    -> 17408
#define W1LO_  54272
#define W2HI_  71680    // [128d][64c] bf16, pitch 144    -> 18432
#define W2LO_  90112
#define ALPS_  108544   // 128 f32
#define B1S_   109056   // 128 f32
#define B2S_   109568   // 64 f32
#define WAS_   109824   // 64 f32
#define BAS_   110080
#define SMEM_BYTES 110096

// ---------------- main kernel ----------------
// grid = 2*B*K (half-tile = 128 px), 256 threads, 2 CTAs/SM.
// Heavy: bf16 hi/lo split mma.sync (HMMA). Warp w owns tile row w (16 px).
__global__ void __launch_bounds__(256, 2)
main_kernel(const float* __restrict__ x,  const float* __restrict__ b1,
            const float* __restrict__ b2, const float* __restrict__ Wa,
            const float* __restrict__ ba, float* __restrict__ out) {
    extern __shared__ char smc[];
    const int blk  = blockIdx.x;
    const int tile = blk >> 1;
    const int half = blk & 1;
    const int b    = tile >> 10;
    const int k    = tile & (K_-1);
    const int gh   = k >> 5, gw = k & 31;
    const int t    = threadIdx.x;

    const int tile_base = b*CHW_ + (gh*T_)*W_ + gw*T_;
    const int rbase = half*8;
    float* heavy = out + HEAVY_OFF;
    float* det   = out + DET_OFF;
    float* alp   = out + ALPHA_OFF;

    if (!g_sel[tile]) {
        // ---- cheap path: heavy = x, detail = 0, alpha = 0 ----
        #pragma unroll 8
        for (int i = t; i < 2048; i += 256) {
            int c = i >> 5; int l = i & 31;
            int off = tile_base + c*HW_ + (rbase + (l >> 2))*W_ + (l & 3)*4;
            float4 v = *(const float4*)(x + off);
            *(float4*)(heavy + off) = v;
            *(float4*)(det   + off) = make_float4(0.f,0.f,0.f,0.f);
        }
        if (t < 32) {
            int aoff = b*HW_ + (gh*T_ + rbase + (t >> 2))*W_ + gw*T_ + (t & 3)*4;
            *(float4*)(alp + aoff) = make_float4(0.f,0.f,0.f,0.f);
        }
        return;
    }

    // ================= staging =================
    // X: bf16 hi/lo split, [px][c] pitch 144B. 4 iters, STS.128 conflict-free.
    #pragma unroll
    for (int it = 0; it < 4; ++it) {
        int s  = it*256 + t;
        int px = s & 127;
        int c8 = s >> 7;                     // 0..7
        int gb = tile_base + (rbase + (px >> 4))*W_ + (px & 15);
        float v[8];
        #pragma unroll
        for (int m = 0; m < 8; ++m) v[m] = x[gb + (c8*8 + m)*HW_];
        u32 h[4], l[4];
        split2(v[0], v[1], h[0], l[0]);
        split2(v[2], v[3], h[1], l[1]);
        split2(v[4], v[5], h[2], l[2]);
        split2(v[6], v[7], h[3], l[3]);
        *(uint4*)(smc + XHI_ + px*144 + c8*16) = make_uint4(h[0],h[1],h[2],h[3]);
        *(uint4*)(smc + XLO_ + px*144 + c8*16) = make_uint4(l[0],l[1],l[2],l[3]);
    }
    // W1: [c][d] pitch 272B
    #pragma unroll
    for (int j = t; j < 2048; j += 256) {
        int c = j >> 5, q = j & 31;
        *(u64*)(smc + W1HI_ + c*272 + q*8) = ((const u64*)g_W1hi)[j];
        *(u64*)(smc + W1LO_ + c*272 + q*8) = ((const u64*)g_W1lo)[j];
    }
    // W2: [d][c] pitch 144B
    #pragma unroll
    for (int j = t; j < 2048; j += 256) {
        int d = j >> 4, q = j & 15;
        *(u64*)(smc + W2HI_ + d*144 + q*8) = ((const u64*)g_W2hi)[j];
        *(u64*)(smc + W2LO_ + d*144 + q*8) = ((const u64*)g_W2lo)[j];
    }
    if (t < HID_) *(float*)(smc + B1S_ + t*4) = b1[t];
    if (t < C_)  { *(float*)(smc + B2S_ + t*4) = b2[t];
                   *(float*)(smc + WAS_ + t*4) = Wa[t]; }
    if (t == 0)   *(float*)(smc + BAS_) = ba[0];
    __syncthreads();

    const u32 sb   = smem_u32(smc);
    const int wid  = t >> 5, lane = t & 31;
    const int px0  = 16*wid;
    const float* b1s = (const float*)(smc + B1S_);
    const float* b2s = (const float*)(smc + B2S_);
    float* alps = (float*)(smc + ALPS_);

    // ---- alpha: lanes 0-15 each handle one of this warp's 16 px ----
    if (lane < 16) {
        int px = px0 + lane;
        float acc = *(const float*)(smc + BAS_);
        const float* was = (const float*)(smc + WAS_);
        #pragma unroll 8
        for (int c2 = 0; c2 < 32; ++c2) {
            u32 hv = *(const u32*)(smc + XHI_ + px*144 + c2*4);
            u32 lv = *(const u32*)(smc + XLO_ + px*144 + c2*4);
            acc = fmaf(bf_lo(hv) + bf_lo(lv), was[2*c2],   acc);
            acc = fmaf(bf_hi(hv) + bf_hi(lv), was[2*c2+1], acc);
        }
        float av = fast_sigmoid(acc);
        alps[px] = av;
        int aoff = b*HW_ + (gh*T_ + rbase + (px >> 4))*W_ + gw*T_ + (px & 15);
        alp[aoff] = av;
    }
    __syncwarp();

    // ---- fragment base addresses (per lane) ----
    const u32 lrow16 = (u32)(lane & 15);
    const u32 lhalf  = (u32)(lane >> 4);
    const u32 xA  = sb + XHI_  + (px0 + lrow16)*144 + lhalf*16;   // +kt*32
    const u32 xAl = sb + XLO_  + (px0 + lrow16)*144 + lhalf*16;
    const u32 w1A = sb + W1HI_ + lrow16*272 + lhalf*16;           // +kt*16*272 + nt*32
    const u32 w1Al= sb + W1LO_ + lrow16*272 + lhalf*16;
    const u32 w2A = sb + W2HI_ + lrow16*144 + lhalf*16;           // +kt*16*144 + nt*32
    const u32 w2Al= sb + W2LO_ + lrow16*144 + lhalf*16;

    // ---- load X fragments (4 k-steps, hi+lo) ----
    u32 xh[4][4], xl[4][4];
    #pragma unroll
    for (int kt = 0; kt < 4; ++kt) {
        ldsm4(xh[kt], xA  + kt*32);
        ldsm4(xl[kt], xAl + kt*32);
    }

    // ---- GEMM1: D1[16px][128d] ----
    float acc[16][4];
    #pragma unroll
    for (int j = 0; j < 16; ++j)
        #pragma unroll
        for (int q = 0; q < 4; ++q) acc[j][q] = 0.f;

    #pragma unroll
    for (int nt = 0; nt < 8; ++nt) {
        #pragma unroll
        for (int kt = 0; kt < 4; ++kt) {
            u32 bh[4], bl_[4];
            ldsm4t(bh,  w1A  + kt*16*272 + nt*32);
            ldsm4t(bl_, w1Al + kt*16*272 + nt*32);
            mma16816(acc[2*nt],   xh[kt], bh[0],  bh[1]);
            mma16816(acc[2*nt],   xh[kt], bl_[0], bl_[1]);
            mma16816(acc[2*nt],   xl[kt], bh[0],  bh[1]);
            mma16816(acc[2*nt+1], xh[kt], bh[2],  bh[3]);
            mma16816(acc[2*nt+1], xh[kt], bl_[2], bl_[3]);
            mma16816(acc[2*nt+1], xl[kt], bh[2],  bh[3]);
        }
    }

    // ---- convert D1 -> H A-fragments in registers (no SMEM round-trip) ----
    const int t2 = (lane & 3)*2;
    u32 ah[8][4], al[8][4];
    #pragma unroll
    for (int kt = 0; kt < 8; ++kt) {
        int dbase = 16*kt + t2;
        float bA0 = b1s[dbase],     bA1 = b1s[dbase+1];
        float bB0 = b1s[dbase+8],   bB1 = b1s[dbase+9];
        float h00 = gelu_tanh(acc[2*kt][0]   + bA0);
        float h01 = gelu_tanh(acc[2*kt][1]   + bA1);
        float h10 = gelu_tanh(acc[2*kt][2]   + bA0);
        float h11 = gelu_tanh(acc[2*kt][3]   + bA1);
        float h20 = gelu_tanh(acc[2*kt+1][0] + bB0);
        float h21 = gelu_tanh(acc[2*kt+1][1] + bB1);
        float h30 = gelu_tanh(acc[2*kt+1][2] + bB0);
        float h31 = gelu_tanh(acc[2*kt+1][3] + bB1);
        split2(h00, h01, ah[kt][0], al[kt][0]);
        split2(h10, h11, ah[kt][1], al[kt][1]);
        split2(h20, h21, ah[kt][2], al[kt][2]);
        split2(h30, h31, ah[kt][3], al[kt][3]);
    }

    // ---- GEMM2: D2[16px][64c] ----
    float acc2[8][4];
    #pragma unroll
    for (int j = 0; j < 8; ++j)
        #pragma unroll
        for (int q = 0; q < 4; ++q) acc2[j][q] = 0.f;

    #pragma unroll
    for (int nt = 0; nt < 4; ++nt) {
        #pragma unroll
        for (int kt = 0; kt < 8; ++kt) {
            u32 bh[4], bl_[4];
            ldsm4t(bh,  w2A  + kt*16*144 + nt*32);
            ldsm4t(bl_, w2Al + kt*16*144 + nt*32);
            mma16816(acc2[2*nt],   ah[kt], bh[0],  bh[1]);
            mma16816(acc2[2*nt],   ah[kt], bl_[0], bl_[1]);
            mma16816(acc2[2*nt],   al[kt], bh[0],  bh[1]);
            mma16816(acc2[2*nt+1], ah[kt], bh[2],  bh[3]);
            mma16816(acc2[2*nt+1], ah[kt], bl_[2], bl_[3]);
            mma16816(acc2[2*nt+1], al[kt], bh[2],  bh[3]);
        }
    }

    // ---- epilogue: det = D2 + b2 ; heavy = x + alpha*det ----
    {
        int g   = lane >> 2;
        int px1 = px0 + g, px2 = px1 + 8;
        float a1v = alps[px1], a2v = alps[px2];
        int ob1 = tile_base + (rbase + wid)*W_ + g;
        int ob2 = ob1 + 8;
        #pragma unroll
        for (int p = 0; p < 4; ++p) {
            #pragma unroll
            for (int s = 0; s < 2; ++s) {
                int jj = 2*p + s;
                int c  = 16*p + 8*s + t2;
                float d0 = acc2[jj][0] + b2s[c];
                float d1 = acc2[jj][1] + b2s[c+1];
                float d2 = acc2[jj][2] + b2s[c];
                float d3 = acc2[jj][3] + b2s[c+1];
                u32 xh1 = *(const u32*)(smc + XHI_ + px1*144 + c*2);
                u32 xl1 = *(const u32*)(smc + XLO_ + px1*144 + c*2);
                u32 xh2 = *(const u32*)(smc + XHI_ + px2*144 + c*2);
                u32 xl2 = *(const u32*)(smc + XLO_ + px2*144 + c*2);
                int o0 = ob1 + c*HW_;
                int o2 = ob2 + c*HW_;
                det[o0]       = d0;
                det[o0 + HW_] = d1;
                det[o2]       = d2;
                det[o2 + HW_] = d3;
                heavy[o0]       = fmaf(a1v, d0, bf_lo(xh1) + bf_lo(xl1));
                heavy[o0 + HW_] = fmaf(a1v, d1, bf_hi(xh1) + bf_hi(xl1));
                heavy[o2]       = fmaf(a2v, d2, bf_lo(xh2) + bf_lo(xl2));
                heavy[o2 + HW_] = fmaf(a2v, d3, bf_hi(xh2) + bf_hi(xl2));
            }
        }
    }
}

// ---------------- launcher ----------------
extern "C" void kernel_launch(void* const* d_in, const int* in_sizes, int n_in,
                              void* d_out, int out_size) {
    const float* x  = (const float*)d_in[0];
    const float* u  = (const float*)d_in[1];
    const float* W1 = (const float*)d_in[2];
    const float* b1 = (const float*)d_in[3];
    const float* W2 = (const float*)d_in[4];
    const float* b2 = (const float*)d_in[5];
    const float* Wa = (const float*)d_in[6];
    const float* ba = (const float*)d_in[7];
    float* out = (float*)d_out;

    cudaFuncSetAttribute(main_kernel,
                         cudaFuncAttributeMaxDynamicSharedMemorySize, SMEM_BYTES);

    prep_kernel<<<35, 256>>>(u, W1, W2, out);
    main_kernel<<<2*B_*K_, 256, SMEM_BYTES>>>(x, b1, b2, Wa, ba, out);
}